// round 16
// baseline (speedup 1.0000x reference)
#include <cuda_runtime.h>
#include <cuda_bf16.h>
#include <math.h>

// Problem constants
#define B_   4
#define S_   2048
#define H_   1024
#define NH_  16
#define D_   64
#define NACT (B_ * S_ * H_)
#define NWGT (H_ * H_)

typedef unsigned long long u64;
typedef unsigned int u32;

// ---------------------------------------------------------------------------
// Scratch (__device__ globals; allocation-free rule)
// ---------------------------------------------------------------------------
__device__ __nv_bfloat16 g_qihi[NACT], g_qilo[NACT];   // input q split / later AO split
__device__ __nv_bfloat16 g_kihi[NACT], g_kilo[NACT];
__device__ __nv_bfloat16 g_vihi[NACT], g_vilo[NACT];
__device__ __nv_bfloat16 g_qphi[NACT], g_qplo[NACT];   // projected [b,h,s,d], pre-scaled 0.125
__device__ __nv_bfloat16 g_kphi[NACT], g_kplo[NACT];
__device__ __nv_bfloat16 g_vphi[NACT], g_vplo[NACT];
__device__ __nv_bfloat16 g_wqhi[NWGT], g_wqlo[NWGT];
__device__ __nv_bfloat16 g_wkhi[NWGT], g_wklo[NWGT];
__device__ __nv_bfloat16 g_wvhi[NWGT], g_wvlo[NWGT];
__device__ __nv_bfloat16 g_wohi[NWGT], g_wolo[NWGT];

__device__ __forceinline__ u32 smem_u32(const void* p) {
    return (u32)__cvta_generic_to_shared(p);
}
__device__ __forceinline__ void cp16(u32 dst, const void* src) {
    asm volatile("cp.async.cg.shared.global [%0], [%1], 16;" :: "r"(dst), "l"(src));
}
#define CP_COMMIT() asm volatile("cp.async.commit_group;")
#define CP_WAIT1()  asm volatile("cp.async.wait_group 1;")
__device__ __forceinline__ void ldsm_x4(u32& r0, u32& r1, u32& r2, u32& r3, u32 addr) {
    asm volatile("ldmatrix.sync.aligned.m8n8.x4.shared.b16 {%0,%1,%2,%3}, [%4];"
                 : "=r"(r0), "=r"(r1), "=r"(r2), "=r"(r3) : "r"(addr));
}
__device__ __forceinline__ void ldsm_x4_t(u32& r0, u32& r1, u32& r2, u32& r3, u32 addr) {
    asm volatile("ldmatrix.sync.aligned.m8n8.x4.trans.shared.b16 {%0,%1,%2,%3}, [%4];"
                 : "=r"(r0), "=r"(r1), "=r"(r2), "=r"(r3) : "r"(addr));
}
__device__ __forceinline__ void mma16816(float* d,
                                         u32 a0, u32 a1, u32 a2, u32 a3,
                                         u32 b0, u32 b1) {
    asm volatile(
        "mma.sync.aligned.m16n8k16.row.col.f32.bf16.bf16.f32 "
        "{%0,%1,%2,%3}, {%4,%5,%6,%7}, {%8,%9}, {%0,%1,%2,%3};"
        : "+f"(d[0]), "+f"(d[1]), "+f"(d[2]), "+f"(d[3])
        : "r"(a0), "r"(a1), "r"(a2), "r"(a3), "r"(b0), "r"(b1));
}
__device__ __forceinline__ void bsplit2(float x, float y, u32& h, u32& l) {
    __nv_bfloat162 hh = __floats2bfloat162_rn(x, y);
    float hx = __bfloat162float(__low2bfloat16(hh));
    float hy = __bfloat162float(__high2bfloat16(hh));
    __nv_bfloat162 ll = __floats2bfloat162_rn(x - hx, y - hy);
    h = *(u32*)&hh; l = *(u32*)&ll;
}

// ---------------------------------------------------------------------------
// fp32 -> bf16 (hi, lo) split
// ---------------------------------------------------------------------------
__global__ __launch_bounds__(256)
void convert_kernel(const float* __restrict__ x,
                    __nv_bfloat16* __restrict__ hi,
                    __nv_bfloat16* __restrict__ lo, int n4)
{
    int i = blockIdx.x * blockDim.x + threadIdx.x;
    if (i >= n4) return;
    float4 v = *(const float4*)(x + 4 * (size_t)i);
    u32 h0, l0, h1, l1;
    bsplit2(v.x, v.y, h0, l0);
    bsplit2(v.z, v.w, h1, l1);
    u32* hp = (u32*)(hi + 4 * (size_t)i);
    u32* lp = (u32*)(lo + 4 * (size_t)i);
    hp[0] = h0; hp[1] = h1;
    lp[0] = l0; lp[1] = l1;
}

// ---------------------------------------------------------------------------
// Tensor-core GEMM, bf16x3 mma.sync, 3-stage cp.async, ONE sync per iter.
// CTA tile 128m x 64n (validated R12 shape). 8 warps = 4m x 2n.
// Stage layout (bytes): Ahi[0,10240) Alo[10240,20480) Bhi[20480,25088) Blo[25088,29696)
//
// Hazard-free ordering (fix of R15's race): at iter i the prefetch targets
// stage (i+2)%3 == (i-1)%3, i.e. the stage read during compute(i-1). The
// prefetch is therefore issued AFTER the iter-i barrier: compute(i-1) is the
// last op of iter i-1 on every thread, so the barrier orders all its reads
// before any iter-i write to that stage. CP_WAIT1 before the barrier retires
// exactly group(it) (groups it, it+1 in flight at that point).
// ---------------------------------------------------------------------------
#define APIT 40
#define BPIT 72
#define G_AHI 0
#define G_ALO 10240
#define G_BHI 20480
#define G_BLO 25088
#define G_STG 29696            // bytes per stage

__global__ __launch_bounds__(256)
void mma_gemm_kernel(const __nv_bfloat16* __restrict__ Ahi_g,
                     const __nv_bfloat16* __restrict__ Alo_g,
                     const __nv_bfloat16* __restrict__ Whi_g,
                     const __nv_bfloat16* __restrict__ Wlo_g,
                     const float* __restrict__ bias,
                     float* __restrict__ Cf,
                     __nv_bfloat16* __restrict__ Chi,
                     __nv_bfloat16* __restrict__ Clo,
                     int layout, float scale)
{
    extern __shared__ __nv_bfloat16 dsm[];
    const u32 smb = smem_u32(dsm);

    const int tid = threadIdx.x;
    const int lane = tid & 31;
    const int wid = tid >> 5;
    const int wm = wid & 3;
    const int wn = wid >> 2;
    const int bm = blockIdx.y * 128;
    const int bn = blockIdx.x * 64;

    const int a_row = tid >> 1;
    const int a_chk = (tid & 1) << 4;
    const int b_row = tid >> 3;
    const int b_chk = (tid & 7) << 3;

    const int a_r = (lane & 15);
    const int a_k = (lane >> 4) << 3;
    u32 aAddr[2];
#pragma unroll
    for (int mi = 0; mi < 2; mi++)
        aAddr[mi] = ((wm * 32 + mi * 16 + a_r) * APIT + a_k) * 2;
    const int b_k = (lane & 15);
    u32 bAddr[2];
#pragma unroll
    for (int nt = 0; nt < 2; nt++)
        bAddr[nt] = (b_k * BPIT + wn * 32 + nt * 16 + ((lane >> 4) << 3)) * 2;

    auto load_tiles = [&](int k0, int stg) {
        const u32 sb = smb + stg * G_STG;
        const size_t ga = (size_t)(bm + a_row) * H_ + k0 + a_chk;
        const u32 sa = (a_row * APIT + a_chk) * 2;
        cp16(sb + G_AHI + sa,      Ahi_g + ga);
        cp16(sb + G_AHI + sa + 16, Ahi_g + ga + 8);
        cp16(sb + G_ALO + sa,      Alo_g + ga);
        cp16(sb + G_ALO + sa + 16, Alo_g + ga + 8);
        const size_t gb = (size_t)(k0 + b_row) * H_ + bn + b_chk;
        const u32 sbo = (b_row * BPIT + b_chk) * 2;
        cp16(sb + G_BHI + sbo, Whi_g + gb);
        cp16(sb + G_BLO + sbo, Wlo_g + gb);
    };

    float acc[2][4][4];
#pragma unroll
    for (int mi = 0; mi < 2; mi++)
#pragma unroll
        for (int ni = 0; ni < 4; ni++)
#pragma unroll
            for (int c = 0; c < 4; c++) acc[mi][ni][c] = 0.f;

    // prime 2 stages
    load_tiles(0, 0);
    CP_COMMIT();
    load_tiles(32, 1);
    CP_COMMIT();

    for (int it = 0; it < 32; it++) {
        const int cur = it % 3;
        CP_WAIT1();          // retires group(it); group(it+1) may still fly
        __syncthreads();     // orders compute(it-1) reads before stage reuse

        if (it + 2 < 32) {   // prefetch AFTER the barrier (stage (it+2)%3 == (it-1)%3)
            load_tiles((it + 2) * 32, (it + 2) % 3);
            CP_COMMIT();
        }

        const u32 sb = smb + cur * G_STG;
#pragma unroll
        for (int s = 0; s < 2; s++) {
            u32 ah[2][4], al[2][4];
#pragma unroll
            for (int mi = 0; mi < 2; mi++) {
                ldsm_x4(ah[mi][0], ah[mi][1], ah[mi][2], ah[mi][3],
                        sb + G_AHI + aAddr[mi] + s * 32);
                ldsm_x4(al[mi][0], al[mi][1], al[mi][2], al[mi][3],
                        sb + G_ALO + aAddr[mi] + s * 32);
            }
            u32 bh[4][2], bl[4][2];
#pragma unroll
            for (int nt = 0; nt < 2; nt++) {
                u32 r0, r1, r2, r3;
                ldsm_x4_t(r0, r1, r2, r3, sb + G_BHI + bAddr[nt] + s * 16 * BPIT * 2);
                bh[nt * 2 + 0][0] = r0; bh[nt * 2 + 0][1] = r1;
                bh[nt * 2 + 1][0] = r2; bh[nt * 2 + 1][1] = r3;
                ldsm_x4_t(r0, r1, r2, r3, sb + G_BLO + bAddr[nt] + s * 16 * BPIT * 2);
                bl[nt * 2 + 0][0] = r0; bl[nt * 2 + 0][1] = r1;
                bl[nt * 2 + 1][0] = r2; bl[nt * 2 + 1][1] = r3;
            }
#pragma unroll
            for (int mi = 0; mi < 2; mi++)
#pragma unroll
                for (int ni = 0; ni < 4; ni++) {
                    float* d = acc[mi][ni];
                    mma16816(d, ah[mi][0], ah[mi][1], ah[mi][2], ah[mi][3], bh[ni][0], bh[ni][1]);
                    mma16816(d, ah[mi][0], ah[mi][1], ah[mi][2], ah[mi][3], bl[ni][0], bl[ni][1]);
                    mma16816(d, al[mi][0], al[mi][1], al[mi][2], al[mi][3], bh[ni][0], bh[ni][1]);
                }
        }
    }

    const int gm0 = bm + wm * 32 + (lane >> 2);
    const int gn_base = bn + wn * 32 + 2 * (lane & 3);
#pragma unroll
    for (int ni = 0; ni < 4; ni++) {
        const int n = gn_base + ni * 8;
        const float2 bv = *(const float2*)(bias + n);
#pragma unroll
        for (int mi = 0; mi < 2; mi++) {
#pragma unroll
            for (int half = 0; half < 2; half++) {
                const int m = gm0 + mi * 16 + half * 8;
                float yx = (acc[mi][ni][2 * half + 0] + bv.x) * scale;
                float yy = (acc[mi][ni][2 * half + 1] + bv.y) * scale;
                if (layout == 0) {
                    *(float2*)(Cf + (size_t)m * H_ + n) = make_float2(yx, yy);
                } else {
                    const int b = m >> 11;
                    const int s = m & (S_ - 1);
                    const int h = n >> 6;
                    const int d = n & (D_ - 1);
                    const size_t ofs = ((size_t)(b * NH_ + h) * S_ + s) * D_ + d;
                    u32 hp, lp;
                    bsplit2(yx, yy, hp, lp);
                    *(u32*)(Chi + ofs) = hp;
                    *(u32*)(Clo + ofs) = lp;
                }
            }
        }
    }
}

// ---------------------------------------------------------------------------
// Tensor-core flash attention (validated R12, unchanged): bf16x3, 2-stage.
// ---------------------------------------------------------------------------
#define KP 72
#define A_MAT (64 * KP * 2)
#define A_STG (4 * A_MAT)

__global__ __launch_bounds__(256)
void attn_mma_kernel(const __nv_bfloat16* __restrict__ qph, const __nv_bfloat16* __restrict__ qpl,
                     const __nv_bfloat16* __restrict__ kph, const __nv_bfloat16* __restrict__ kpl,
                     const __nv_bfloat16* __restrict__ vph, const __nv_bfloat16* __restrict__ vpl,
                     __nv_bfloat16* __restrict__ aoh, __nv_bfloat16* __restrict__ aol)
{
    extern __shared__ __nv_bfloat16 dsm[];
    const u32 smb = smem_u32(dsm);

    const int tid = threadIdx.x;
    const int lane = tid & 31;
    const int w = tid >> 5;
    const int bh = blockIdx.y;
    const int qt = blockIdx.x * 128;
    const size_t base = (size_t)bh * S_ * D_;

#pragma unroll
    for (int t = 0; t < 4; t++) {
        const int idx = t * 256 + tid;
        const int row = idx >> 3, c8 = (idx & 7) << 3;
        const size_t g = base + (size_t)(qt + row) * D_ + c8;
        *(uint4*)&dsm[row * KP + c8]            = *(const uint4*)(qph + g);
        *(uint4*)&dsm[128 * KP + row * KP + c8] = *(const uint4*)(qpl + g);
    }
    __syncthreads();

    u32 qfh[4][4], qfl[4][4];
    {
        const int r = lane & 15, ko = (lane >> 4) << 3;
#pragma unroll
        for (int s = 0; s < 4; s++) {
            const u32 addr = smb + (((w * 16 + r) * KP) + s * 16 + ko) * 2;
            ldsm_x4(qfh[s][0], qfh[s][1], qfh[s][2], qfh[s][3], addr);
            ldsm_x4(qfl[s][0], qfl[s][1], qfl[s][2], qfl[s][3], addr + 128 * KP * 2);
        }
    }
    __syncthreads();

    const __nv_bfloat16* mats[4] = {kph, kpl, vph, vpl};
    auto load_kv = [&](int kv0, int stg) {
#pragma unroll
        for (int t = 0; t < 8; t++) {
            const int mat = t >> 1;
            const int idx = t * 256 + tid;
            const int row = (idx >> 3) & 63;
            const int c8 = (idx & 7) << 3;
            const u32 dst = smb + stg * A_STG + mat * A_MAT + (row * KP + c8) * 2;
            cp16(dst, mats[mat] + base + (size_t)(kv0 + row) * D_ + c8);
        }
    };

    float oacc[8][4];
#pragma unroll
    for (int j = 0; j < 8; j++)
#pragma unroll
        for (int c = 0; c < 4; c++) oacc[j][c] = 0.f;
    float m_lo = -1e30f, m_hi = -1e30f, l_lo = 0.f, l_hi = 0.f;

    const int k_row = ((lane >> 4) << 3) + (lane & 7);
    const int k_col = ((lane >> 3) & 1) << 3;
    const int v_row = lane & 15;
    const int v_col = (lane >> 4) << 3;

    load_kv(0, 0);
    CP_COMMIT();

    for (int it = 0; it < 32; it++) {
        const int cur = it & 1;
        if (it < 31) load_kv((it + 1) * 64, 1 - cur);
        CP_COMMIT();
        CP_WAIT1();
        __syncthreads();

        const u32 sb = smb + cur * A_STG;

        float sacc[8][4];
#pragma unroll
        for (int j = 0; j < 8; j++)
#pragma unroll
            for (int c = 0; c < 4; c++) sacc[j][c] = 0.f;

#pragma unroll
        for (int s = 0; s < 4; s++) {
#pragma unroll
            for (int jp = 0; jp < 4; jp++) {
                u32 h0, h1, h2, h3, l0, l1, l2, l3;
                const u32 addr = sb + ((jp * 16 + k_row) * KP + s * 16 + k_col) * 2;
                ldsm_x4(h0, h1, h2, h3, addr);
                ldsm_x4(l0, l1, l2, l3, addr + A_MAT);
                mma16816(sacc[2 * jp],     qfh[s][0], qfh[s][1], qfh[s][2], qfh[s][3], h0, h1);
                mma16816(sacc[2 * jp],     qfh[s][0], qfh[s][1], qfh[s][2], qfh[s][3], l0, l1);
                mma16816(sacc[2 * jp],     qfl[s][0], qfl[s][1], qfl[s][2], qfl[s][3], h0, h1);
                mma16816(sacc[2 * jp + 1], qfh[s][0], qfh[s][1], qfh[s][2], qfh[s][3], h2, h3);
                mma16816(sacc[2 * jp + 1], qfh[s][0], qfh[s][1], qfh[s][2], qfh[s][3], l2, l3);
                mma16816(sacc[2 * jp + 1], qfl[s][0], qfl[s][1], qfl[s][2], qfl[s][3], h2, h3);
            }
        }

        float mt_lo = -1e30f, mt_hi = -1e30f;
#pragma unroll
        for (int j = 0; j < 8; j++) {
            mt_lo = fmaxf(mt_lo, fmaxf(sacc[j][0], sacc[j][1]));
            mt_hi = fmaxf(mt_hi, fmaxf(sacc[j][2], sacc[j][3]));
        }
        mt_lo = fmaxf(mt_lo, __shfl_xor_sync(0xffffffffu, mt_lo, 1));
        mt_lo = fmaxf(mt_lo, __shfl_xor_sync(0xffffffffu, mt_lo, 2));
        mt_hi = fmaxf(mt_hi, __shfl_xor_sync(0xffffffffu, mt_hi, 1));
        mt_hi = fmaxf(mt_hi, __shfl_xor_sync(0xffffffffu, mt_hi, 2));

        const float mn_lo = fmaxf(m_lo, mt_lo), mn_hi = fmaxf(m_hi, mt_hi);
        const float f_lo = __expf(m_lo - mn_lo), f_hi = __expf(m_hi - mn_hi);
        float rs_lo = 0.f, rs_hi = 0.f;
#pragma unroll
        for (int j = 0; j < 8; j++) {
            sacc[j][0] = __expf(sacc[j][0] - mn_lo);
            sacc[j][1] = __expf(sacc[j][1] - mn_lo);
            sacc[j][2] = __expf(sacc[j][2] - mn_hi);
            sacc[j][3] = __expf(sacc[j][3] - mn_hi);
            rs_lo += sacc[j][0] + sacc[j][1];
            rs_hi += sacc[j][2] + sacc[j][3];
        }
        rs_lo += __shfl_xor_sync(0xffffffffu, rs_lo, 1);
        rs_lo += __shfl_xor_sync(0xffffffffu, rs_lo, 2);
        rs_hi += __shfl_xor_sync(0xffffffffu, rs_hi, 1);
        rs_hi += __shfl_xor_sync(0xffffffffu, rs_hi, 2);
        l_lo = l_lo * f_lo + rs_lo;  m_lo = mn_lo;
        l_hi = l_hi * f_hi + rs_hi;  m_hi = mn_hi;
#pragma unroll
        for (int j = 0; j < 8; j++) {
            oacc[j][0] *= f_lo; oacc[j][1] *= f_lo;
            oacc[j][2] *= f_hi; oacc[j][3] *= f_hi;
        }

#pragma unroll
        for (int t = 0; t < 4; t++) {
            u32 ph[4], pl[4];
            bsplit2(sacc[2 * t][0],     sacc[2 * t][1],     ph[0], pl[0]);
            bsplit2(sacc[2 * t][2],     sacc[2 * t][3],     ph[1], pl[1]);
            bsplit2(sacc[2 * t + 1][0], sacc[2 * t + 1][1], ph[2], pl[2]);
            bsplit2(sacc[2 * t + 1][2], sacc[2 * t + 1][3], ph[3], pl[3]);
#pragma unroll
            for (int up = 0; up < 4; up++) {
                u32 h0, h1, h2, h3, l0, l1, l2, l3;
                const u32 addr = sb + 2 * A_MAT + ((t * 16 + v_row) * KP + up * 16 + v_col) * 2;
                ldsm_x4_t(h0, h1, h2, h3, addr);
                ldsm_x4_t(l0, l1, l2, l3, addr + A_MAT);
                mma16816(oacc[2 * up],     ph[0], ph[1], ph[2], ph[3], h0, h1);
                mma16816(oacc[2 * up],     pl[0], pl[1], pl[2], pl[3], h0, h1);
                mma16816(oacc[2 * up],     ph[0], ph[1], ph[2], ph[3], l0, l1);
                mma16816(oacc[2 * up + 1], ph[0], ph[1], ph[2], ph[3], h2, h3);
                mma16816(oacc[2 * up + 1], pl[0], pl[1], pl[2], pl[3], h2, h3);
                mma16816(oacc[2 * up + 1], ph[0], ph[1], ph[2], ph[3], l2, l3);
            }
        }
        __syncthreads();
    }

    const float il_lo = 1.f / l_lo, il_hi = 1.f / l_hi;
    const int r_lo = qt + w * 16 + (lane >> 2);
    const int r_hi = r_lo + 8;
    const int b = bh >> 4, h = bh & 15;
    const int colb = h * 64 + 2 * (lane & 3);
#pragma unroll
    for (int j = 0; j < 8; j++) {
        const int col = colb + j * 8;
        u32 hp, lp;
        bsplit2(oacc[j][0] * il_lo, oacc[j][1] * il_lo, hp, lp);
        size_t ofs = (size_t)(b * S_ + r_lo) * H_ + col;
        *(u32*)(aoh + ofs) = hp;
        *(u32*)(aol + ofs) = lp;
        bsplit2(oacc[j][2] * il_hi, oacc[j][3] * il_hi, hp, lp);
        ofs = (size_t)(b * S_ + r_hi) * H_ + col;
        *(u32*)(aoh + ofs) = hp;
        *(u32*)(aol + ofs) = lp;
    }
}

// ---------------------------------------------------------------------------
// kernel_launch
// ---------------------------------------------------------------------------
extern "C" void kernel_launch(void* const* d_in, const int* in_sizes, int n_in,
                              void* d_out, int out_size)
{
    const float* q  = (const float*)d_in[0];
    const float* k  = (const float*)d_in[1];
    const float* v  = (const float*)d_in[2];
    const float* wq = (const float*)d_in[3];
    const float* bq = (const float*)d_in[4];
    const float* wk = (const float*)d_in[5];
    const float* bk = (const float*)d_in[6];
    const float* wv = (const float*)d_in[7];
    const float* bv = (const float*)d_in[8];
    const float* wo = (const float*)d_in[9];
    const float* bo = (const float*)d_in[10];
    float* out = (float*)d_out;

    __nv_bfloat16 *qihi, *qilo, *kihi, *kilo, *vihi, *vilo;
    __nv_bfloat16 *qphi, *qplo, *kphi, *kplo, *vphi, *vplo;
    __nv_bfloat16 *wqhi, *wqlo, *wkhi, *wklo, *wvhi, *wvlo, *wohi, *wolo;
    cudaGetSymbolAddress((void**)&qihi, g_qihi); cudaGetSymbolAddress((void**)&qilo, g_qilo);
    cudaGetSymbolAddress((void**)&kihi, g_kihi); cudaGetSymbolAddress((void**)&kilo, g_kilo);
    cudaGetSymbolAddress((void**)&vihi, g_vihi); cudaGetSymbolAddress((void**)&vilo, g_vilo);
    cudaGetSymbolAddress((void**)&qphi, g_qphi); cudaGetSymbolAddress((void**)&qplo, g_qplo);
    cudaGetSymbolAddress((void**)&kphi, g_kphi); cudaGetSymbolAddress((void**)&kplo, g_kplo);
    cudaGetSymbolAddress((void**)&vphi, g_vphi); cudaGetSymbolAddress((void**)&vplo, g_vplo);
    cudaGetSymbolAddress((void**)&wqhi, g_wqhi); cudaGetSymbolAddress((void**)&wqlo, g_wqlo);
    cudaGetSymbolAddress((void**)&wkhi, g_wkhi); cudaGetSymbolAddress((void**)&wklo, g_wklo);
    cudaGetSymbolAddress((void**)&wvhi, g_wvhi); cudaGetSymbolAddress((void**)&wvlo, g_wvlo);
    cudaGetSymbolAddress((void**)&wohi, g_wohi); cudaGetSymbolAddress((void**)&wolo, g_wolo);
    __nv_bfloat16 *aohi = qihi, *aolo = qilo;   // AO reuses q-input split buffers

    const int gemm_smem = 3 * G_STG;     // 89,088 B
    const int attn_smem = 2 * A_STG;     // 73,728 B
    cudaFuncSetAttribute(mma_gemm_kernel, cudaFuncAttributeMaxDynamicSharedMemorySize, gemm_smem);
    cudaFuncSetAttribute(attn_mma_kernel, cudaFuncAttributeMaxDynamicSharedMemorySize, attn_smem);

    const int actBlocks = (NACT / 4 + 255) / 256;
    const int wgtBlocks = (NWGT / 4 + 255) / 256;

    convert_kernel<<<actBlocks, 256>>>(q,  qihi, qilo, NACT / 4);
    convert_kernel<<<actBlocks, 256>>>(k,  kihi, kilo, NACT / 4);
    convert_kernel<<<actBlocks, 256>>>(v,  vihi, vilo, NACT / 4);
    convert_kernel<<<wgtBlocks, 256>>>(wq, wqhi, wqlo, NWGT / 4);
    convert_kernel<<<wgtBlocks, 256>>>(wk, wkhi, wklo, NWGT / 4);
    convert_kernel<<<wgtBlocks, 256>>>(wv, wvhi, wvlo, NWGT / 4);
    convert_kernel<<<wgtBlocks, 256>>>(wo, wohi, wolo, NWGT / 4);

    dim3 gg(16, 64), bb(256);
    mma_gemm_kernel<<<gg, bb, gemm_smem>>>(qihi, qilo, wqhi, wqlo, bq, nullptr, qphi, qplo, 1, 0.125f);
    mma_gemm_kernel<<<gg, bb, gemm_smem>>>(kihi, kilo, wkhi, wklo, bk, nullptr, kphi, kplo, 1, 1.0f);
    mma_gemm_kernel<<<gg, bb, gemm_smem>>>(vihi, vilo, wvhi, wvlo, bv, nullptr, vphi, vplo, 1, 1.0f);

    attn_mma_kernel<<<dim3(16, 64), 256, attn_smem>>>(qphi, qplo, kphi, kplo, vphi, vplo, aohi, aolo);

    mma_gemm_kernel<<<gg, bb, gemm_smem>>>(aohi, aolo, wohi, wolo, bo, out, nullptr, nullptr, 0, 1.0f);
}

// round 17
// speedup vs baseline: 1.0357x; 1.0357x over previous
#include <cuda_runtime.h>
#include <cuda_bf16.h>
#include <math.h>

// Problem constants
#define B_   4
#define S_   2048
#define H_   1024
#define NH_  16
#define D_   64
#define NACT (B_ * S_ * H_)
#define NWGT (H_ * H_)
#define LOG2E 1.44269504088896340736f

typedef unsigned long long u64;
typedef unsigned int u32;

// ---------------------------------------------------------------------------
// Scratch (__device__ globals; allocation-free rule)
// ---------------------------------------------------------------------------
__device__ __nv_bfloat16 g_qihi[NACT], g_qilo[NACT];   // input q split / later AO split
__device__ __nv_bfloat16 g_kihi[NACT], g_kilo[NACT];
__device__ __nv_bfloat16 g_vihi[NACT], g_vilo[NACT];
__device__ __nv_bfloat16 g_qphi[NACT], g_qplo[NACT];   // projected [b,h,s,d], scaled 0.125*log2e
__device__ __nv_bfloat16 g_kphi[NACT], g_kplo[NACT];
__device__ __nv_bfloat16 g_vphi[NACT], g_vplo[NACT];
__device__ __nv_bfloat16 g_wqhi[NWGT], g_wqlo[NWGT];
__device__ __nv_bfloat16 g_wkhi[NWGT], g_wklo[NWGT];
__device__ __nv_bfloat16 g_wvhi[NWGT], g_wvlo[NWGT];
__device__ __nv_bfloat16 g_wohi[NWGT], g_wolo[NWGT];

__device__ __forceinline__ u32 smem_u32(const void* p) {
    return (u32)__cvta_generic_to_shared(p);
}
__device__ __forceinline__ void cp16(u32 dst, const void* src) {
    asm volatile("cp.async.cg.shared.global [%0], [%1], 16;" :: "r"(dst), "l"(src));
}
#define CP_COMMIT() asm volatile("cp.async.commit_group;")
#define CP_WAIT1()  asm volatile("cp.async.wait_group 1;")
__device__ __forceinline__ void ldsm_x4(u32& r0, u32& r1, u32& r2, u32& r3, u32 addr) {
    asm volatile("ldmatrix.sync.aligned.m8n8.x4.shared.b16 {%0,%1,%2,%3}, [%4];"
                 : "=r"(r0), "=r"(r1), "=r"(r2), "=r"(r3) : "r"(addr));
}
__device__ __forceinline__ void ldsm_x4_t(u32& r0, u32& r1, u32& r2, u32& r3, u32 addr) {
    asm volatile("ldmatrix.sync.aligned.m8n8.x4.trans.shared.b16 {%0,%1,%2,%3}, [%4];"
                 : "=r"(r0), "=r"(r1), "=r"(r2), "=r"(r3) : "r"(addr));
}
__device__ __forceinline__ void mma16816(float* d,
                                         u32 a0, u32 a1, u32 a2, u32 a3,
                                         u32 b0, u32 b1) {
    asm volatile(
        "mma.sync.aligned.m16n8k16.row.col.f32.bf16.bf16.f32 "
        "{%0,%1,%2,%3}, {%4,%5,%6,%7}, {%8,%9}, {%0,%1,%2,%3};"
        : "+f"(d[0]), "+f"(d[1]), "+f"(d[2]), "+f"(d[3])
        : "r"(a0), "r"(a1), "r"(a2), "r"(a3), "r"(b0), "r"(b1));
}
__device__ __forceinline__ void bsplit2(float x, float y, u32& h, u32& l) {
    __nv_bfloat162 hh = __floats2bfloat162_rn(x, y);
    float hx = __bfloat162float(__low2bfloat16(hh));
    float hy = __bfloat162float(__high2bfloat16(hh));
    __nv_bfloat162 ll = __floats2bfloat162_rn(x - hx, y - hy);
    h = *(u32*)&hh; l = *(u32*)&ll;
}
__device__ __forceinline__ float ex2(float x) {
    float r;
    asm("ex2.approx.f32 %0, %1;" : "=f"(r) : "f"(x));
    return r;
}

// ---------------------------------------------------------------------------
// Batched fp32 -> bf16 (hi, lo) splits. blockIdx.y selects the tensor.
// ---------------------------------------------------------------------------
__global__ __launch_bounds__(256)
void convert3_kernel(const float* __restrict__ x0, const float* __restrict__ x1,
                     const float* __restrict__ x2,
                     __nv_bfloat16* __restrict__ h0, __nv_bfloat16* __restrict__ l0,
                     __nv_bfloat16* __restrict__ h1, __nv_bfloat16* __restrict__ l1,
                     __nv_bfloat16* __restrict__ h2, __nv_bfloat16* __restrict__ l2,
                     int n4)
{
    int i = blockIdx.x * blockDim.x + threadIdx.x;
    if (i >= n4) return;
    const float* x = (blockIdx.y == 0) ? x0 : (blockIdx.y == 1) ? x1 : x2;
    __nv_bfloat16* hi = (blockIdx.y == 0) ? h0 : (blockIdx.y == 1) ? h1 : h2;
    __nv_bfloat16* lo = (blockIdx.y == 0) ? l0 : (blockIdx.y == 1) ? l1 : l2;
    float4 v = *(const float4*)(x + 4 * (size_t)i);
    u32 a0, b0, a1, b1;
    bsplit2(v.x, v.y, a0, b0);
    bsplit2(v.z, v.w, a1, b1);
    u32* hp = (u32*)(hi + 4 * (size_t)i);
    u32* lp = (u32*)(lo + 4 * (size_t)i);
    hp[0] = a0; hp[1] = a1;
    lp[0] = b0; lp[1] = b1;
}

__global__ __launch_bounds__(256)
void convert4_kernel(const float* __restrict__ x0, const float* __restrict__ x1,
                     const float* __restrict__ x2, const float* __restrict__ x3,
                     __nv_bfloat16* __restrict__ h0, __nv_bfloat16* __restrict__ l0,
                     __nv_bfloat16* __restrict__ h1, __nv_bfloat16* __restrict__ l1,
                     __nv_bfloat16* __restrict__ h2, __nv_bfloat16* __restrict__ l2,
                     __nv_bfloat16* __restrict__ h3, __nv_bfloat16* __restrict__ l3,
                     int n4)
{
    int i = blockIdx.x * blockDim.x + threadIdx.x;
    if (i >= n4) return;
    const float* x = (blockIdx.y == 0) ? x0 : (blockIdx.y == 1) ? x1
                   : (blockIdx.y == 2) ? x2 : x3;
    __nv_bfloat16* hi = (blockIdx.y == 0) ? h0 : (blockIdx.y == 1) ? h1
                      : (blockIdx.y == 2) ? h2 : h3;
    __nv_bfloat16* lo = (blockIdx.y == 0) ? l0 : (blockIdx.y == 1) ? l1
                      : (blockIdx.y == 2) ? l2 : l3;
    float4 v = *(const float4*)(x + 4 * (size_t)i);
    u32 a0, b0, a1, b1;
    bsplit2(v.x, v.y, a0, b0);
    bsplit2(v.z, v.w, a1, b1);
    u32* hp = (u32*)(hi + 4 * (size_t)i);
    u32* lp = (u32*)(lo + 4 * (size_t)i);
    hp[0] = a0; hp[1] = a1;
    lp[0] = b0; lp[1] = b1;
}

// ---------------------------------------------------------------------------
// Tensor-core GEMM (byte-identical R12): bf16x3 mma.sync, 2-stage cp.async.
// ---------------------------------------------------------------------------
#define APIT 40
#define BPIT 72
#define G_AHI 0
#define G_ALO 10240
#define G_BHI 20480
#define G_BLO 25088
#define G_STG 29696            // bytes per stage

__global__ __launch_bounds__(256)
void mma_gemm_kernel(const __nv_bfloat16* __restrict__ Ahi_g,
                     const __nv_bfloat16* __restrict__ Alo_g,
                     const __nv_bfloat16* __restrict__ Whi_g,
                     const __nv_bfloat16* __restrict__ Wlo_g,
                     const float* __restrict__ bias,
                     float* __restrict__ Cf,
                     __nv_bfloat16* __restrict__ Chi,
                     __nv_bfloat16* __restrict__ Clo,
                     int layout, float scale)
{
    extern __shared__ __nv_bfloat16 dsm[];
    const u32 smb = smem_u32(dsm);

    const int tid = threadIdx.x;
    const int lane = tid & 31;
    const int wid = tid >> 5;
    const int wm = wid & 3;
    const int wn = wid >> 2;
    const int bm = blockIdx.y * 128;
    const int bn = blockIdx.x * 64;

    const int a_row = tid >> 1;
    const int a_chk = (tid & 1) << 4;
    const int b_row = tid >> 3;
    const int b_chk = (tid & 7) << 3;

    const int a_r = (lane & 15);
    const int a_k = (lane >> 4) << 3;
    u32 aAddr[2];
#pragma unroll
    for (int mi = 0; mi < 2; mi++)
        aAddr[mi] = ((wm * 32 + mi * 16 + a_r) * APIT + a_k) * 2;
    const int b_k = (lane & 15);
    u32 bAddr[2];
#pragma unroll
    for (int nt = 0; nt < 2; nt++)
        bAddr[nt] = (b_k * BPIT + wn * 32 + nt * 16 + ((lane >> 4) << 3)) * 2;

    auto load_tiles = [&](int k0, int stg) {
        const u32 sb = smb + stg * G_STG;
        const size_t ga = (size_t)(bm + a_row) * H_ + k0 + a_chk;
        const u32 sa = (a_row * APIT + a_chk) * 2;
        cp16(sb + G_AHI + sa,      Ahi_g + ga);
        cp16(sb + G_AHI + sa + 16, Ahi_g + ga + 8);
        cp16(sb + G_ALO + sa,      Alo_g + ga);
        cp16(sb + G_ALO + sa + 16, Alo_g + ga + 8);
        const size_t gb = (size_t)(k0 + b_row) * H_ + bn + b_chk;
        const u32 sbo = (b_row * BPIT + b_chk) * 2;
        cp16(sb + G_BHI + sbo, Whi_g + gb);
        cp16(sb + G_BLO + sbo, Wlo_g + gb);
    };

    float acc[2][4][4];
#pragma unroll
    for (int mi = 0; mi < 2; mi++)
#pragma unroll
        for (int ni = 0; ni < 4; ni++)
#pragma unroll
            for (int c = 0; c < 4; c++) acc[mi][ni][c] = 0.f;

    load_tiles(0, 0);
    CP_COMMIT();

    for (int it = 0; it < 32; it++) {
        const int cur = it & 1;
        if (it < 31) load_tiles((it + 1) * 32, 1 - cur);
        CP_COMMIT();
        CP_WAIT1();
        __syncthreads();

        const u32 sb = smb + cur * G_STG;
#pragma unroll
        for (int s = 0; s < 2; s++) {
            u32 ah[2][4], al[2][4];
#pragma unroll
            for (int mi = 0; mi < 2; mi++) {
                ldsm_x4(ah[mi][0], ah[mi][1], ah[mi][2], ah[mi][3],
                        sb + G_AHI + aAddr[mi] + s * 32);
                ldsm_x4(al[mi][0], al[mi][1], al[mi][2], al[mi][3],
                        sb + G_ALO + aAddr[mi] + s * 32);
            }
            u32 bh[4][2], bl[4][2];
#pragma unroll
            for (int nt = 0; nt < 2; nt++) {
                u32 r0, r1, r2, r3;
                ldsm_x4_t(r0, r1, r2, r3, sb + G_BHI + bAddr[nt] + s * 16 * BPIT * 2);
                bh[nt * 2 + 0][0] = r0; bh[nt * 2 + 0][1] = r1;
                bh[nt * 2 + 1][0] = r2; bh[nt * 2 + 1][1] = r3;
                ldsm_x4_t(r0, r1, r2, r3, sb + G_BLO + bAddr[nt] + s * 16 * BPIT * 2);
                bl[nt * 2 + 0][0] = r0; bl[nt * 2 + 0][1] = r1;
                bl[nt * 2 + 1][0] = r2; bl[nt * 2 + 1][1] = r3;
            }
#pragma unroll
            for (int mi = 0; mi < 2; mi++)
#pragma unroll
                for (int ni = 0; ni < 4; ni++) {
                    float* d = acc[mi][ni];
                    mma16816(d, ah[mi][0], ah[mi][1], ah[mi][2], ah[mi][3], bh[ni][0], bh[ni][1]);
                    mma16816(d, ah[mi][0], ah[mi][1], ah[mi][2], ah[mi][3], bl[ni][0], bl[ni][1]);
                    mma16816(d, al[mi][0], al[mi][1], al[mi][2], al[mi][3], bh[ni][0], bh[ni][1]);
                }
        }
        __syncthreads();
    }

    const int gm0 = bm + wm * 32 + (lane >> 2);
    const int gn_base = bn + wn * 32 + 2 * (lane & 3);
#pragma unroll
    for (int ni = 0; ni < 4; ni++) {
        const int n = gn_base + ni * 8;
        const float2 bv = *(const float2*)(bias + n);
#pragma unroll
        for (int mi = 0; mi < 2; mi++) {
#pragma unroll
            for (int half = 0; half < 2; half++) {
                const int m = gm0 + mi * 16 + half * 8;
                float yx = (acc[mi][ni][2 * half + 0] + bv.x) * scale;
                float yy = (acc[mi][ni][2 * half + 1] + bv.y) * scale;
                if (layout == 0) {
                    *(float2*)(Cf + (size_t)m * H_ + n) = make_float2(yx, yy);
                } else {
                    const int b = m >> 11;
                    const int s = m & (S_ - 1);
                    const int h = n >> 6;
                    const int d = n & (D_ - 1);
                    const size_t ofs = ((size_t)(b * NH_ + h) * S_ + s) * D_ + d;
                    u32 hp, lp;
                    bsplit2(yx, yy, hp, lp);
                    *(u32*)(Chi + ofs) = hp;
                    *(u32*)(Clo + ofs) = lp;
                }
            }
        }
    }
}

// ---------------------------------------------------------------------------
// Tensor-core flash attention (R12 structure). Q carries 0.125*log2e, so the
// softmax runs in the log2 domain: p = ex2(s'-m'), f = ex2(m'old-m'new).
// ---------------------------------------------------------------------------
#define KP 72
#define A_MAT (64 * KP * 2)
#define A_STG (4 * A_MAT)

__global__ __launch_bounds__(256)
void attn_mma_kernel(const __nv_bfloat16* __restrict__ qph, const __nv_bfloat16* __restrict__ qpl,
                     const __nv_bfloat16* __restrict__ kph, const __nv_bfloat16* __restrict__ kpl,
                     const __nv_bfloat16* __restrict__ vph, const __nv_bfloat16* __restrict__ vpl,
                     __nv_bfloat16* __restrict__ aoh, __nv_bfloat16* __restrict__ aol)
{
    extern __shared__ __nv_bfloat16 dsm[];
    const u32 smb = smem_u32(dsm);

    const int tid = threadIdx.x;
    const int lane = tid & 31;
    const int w = tid >> 5;
    const int bh = blockIdx.y;
    const int qt = blockIdx.x * 128;
    const size_t base = (size_t)bh * S_ * D_;

#pragma unroll
    for (int t = 0; t < 4; t++) {
        const int idx = t * 256 + tid;
        const int row = idx >> 3, c8 = (idx & 7) << 3;
        const size_t g = base + (size_t)(qt + row) * D_ + c8;
        *(uint4*)&dsm[row * KP + c8]            = *(const uint4*)(qph + g);
        *(uint4*)&dsm[128 * KP + row * KP + c8] = *(const uint4*)(qpl + g);
    }
    __syncthreads();

    u32 qfh[4][4], qfl[4][4];
    {
        const int r = lane & 15, ko = (lane >> 4) << 3;
#pragma unroll
        for (int s = 0; s < 4; s++) {
            const u32 addr = smb + (((w * 16 + r) * KP) + s * 16 + ko) * 2;
            ldsm_x4(qfh[s][0], qfh[s][1], qfh[s][2], qfh[s][3], addr);
            ldsm_x4(qfl[s][0], qfl[s][1], qfl[s][2], qfl[s][3], addr + 128 * KP * 2);
        }
    }
    __syncthreads();

    const __nv_bfloat16* mats[4] = {kph, kpl, vph, vpl};
    auto load_kv = [&](int kv0, int stg) {
#pragma unroll
        for (int t = 0; t < 8; t++) {
            const int mat = t >> 1;
            const int idx = t * 256 + tid;
            const int row = (idx >> 3) & 63;
            const int c8 = (idx & 7) << 3;
            const u32 dst = smb + stg * A_STG + mat * A_MAT + (row * KP + c8) * 2;
            cp16(dst, mats[mat] + base + (size_t)(kv0 + row) * D_ + c8);
        }
    };

    float oacc[8][4];
#pragma unroll
    for (int j = 0; j < 8; j++)
#pragma unroll
        for (int c = 0; c < 4; c++) oacc[j][c] = 0.f;
    float m_lo = -1e30f, m_hi = -1e30f, l_lo = 0.f, l_hi = 0.f;

    const int k_row = ((lane >> 4) << 3) + (lane & 7);
    const int k_col = ((lane >> 3) & 1) << 3;
    const int v_row = lane & 15;
    const int v_col = (lane >> 4) << 3;

    load_kv(0, 0);
    CP_COMMIT();

    for (int it = 0; it < 32; it++) {
        const int cur = it & 1;
        if (it < 31) load_kv((it + 1) * 64, 1 - cur);
        CP_COMMIT();
        CP_WAIT1();
        __syncthreads();

        const u32 sb = smb + cur * A_STG;

        float sacc[8][4];
#pragma unroll
        for (int j = 0; j < 8; j++)
#pragma unroll
            for (int c = 0; c < 4; c++) sacc[j][c] = 0.f;

#pragma unroll
        for (int s = 0; s < 4; s++) {
#pragma unroll
            for (int jp = 0; jp < 4; jp++) {
                u32 h0, h1, h2, h3, l0, l1, l2, l3;
                const u32 addr = sb + ((jp * 16 + k_row) * KP + s * 16 + k_col) * 2;
                ldsm_x4(h0, h1, h2, h3, addr);
                ldsm_x4(l0, l1, l2, l3, addr + A_MAT);
                mma16816(sacc[2 * jp],     qfh[s][0], qfh[s][1], qfh[s][2], qfh[s][3], h0, h1);
                mma16816(sacc[2 * jp],     qfh[s][0], qfh[s][1], qfh[s][2], qfh[s][3], l0, l1);
                mma16816(sacc[2 * jp],     qfl[s][0], qfl[s][1], qfl[s][2], qfl[s][3], h0, h1);
                mma16816(sacc[2 * jp + 1], qfh[s][0], qfh[s][1], qfh[s][2], qfh[s][3], h2, h3);
                mma16816(sacc[2 * jp + 1], qfh[s][0], qfh[s][1], qfh[s][2], qfh[s][3], l2, l3);
                mma16816(sacc[2 * jp + 1], qfl[s][0], qfl[s][1], qfl[s][2], qfl[s][3], h2, h3);
            }
        }

        float mt_lo = -1e30f, mt_hi = -1e30f;
#pragma unroll
        for (int j = 0; j < 8; j++) {
            mt_lo = fmaxf(mt_lo, fmaxf(sacc[j][0], sacc[j][1]));
            mt_hi = fmaxf(mt_hi, fmaxf(sacc[j][2], sacc[j][3]));
        }
        mt_lo = fmaxf(mt_lo, __shfl_xor_sync(0xffffffffu, mt_lo, 1));
        mt_lo = fmaxf(mt_lo, __shfl_xor_sync(0xffffffffu, mt_lo, 2));
        mt_hi = fmaxf(mt_hi, __shfl_xor_sync(0xffffffffu, mt_hi, 1));
        mt_hi = fmaxf(mt_hi, __shfl_xor_sync(0xffffffffu, mt_hi, 2));

        const float mn_lo = fmaxf(m_lo, mt_lo), mn_hi = fmaxf(m_hi, mt_hi);
        const float f_lo = ex2(m_lo - mn_lo), f_hi = ex2(m_hi - mn_hi);
        float rs_lo = 0.f, rs_hi = 0.f;
#pragma unroll
        for (int j = 0; j < 8; j++) {
            sacc[j][0] = ex2(sacc[j][0] - mn_lo);
            sacc[j][1] = ex2(sacc[j][1] - mn_lo);
            sacc[j][2] = ex2(sacc[j][2] - mn_hi);
            sacc[j][3] = ex2(sacc[j][3] - mn_hi);
            rs_lo += sacc[j][0] + sacc[j][1];
            rs_hi += sacc[j][2] + sacc[j][3];
        }
        rs_lo += __shfl_xor_sync(0xffffffffu, rs_lo, 1);
        rs_lo += __shfl_xor_sync(0xffffffffu, rs_lo, 2);
        rs_hi += __shfl_xor_sync(0xffffffffu, rs_hi, 1);
        rs_hi += __shfl_xor_sync(0xffffffffu, rs_hi, 2);
        l_lo = l_lo * f_lo + rs_lo;  m_lo = mn_lo;
        l_hi = l_hi * f_hi + rs_hi;  m_hi = mn_hi;
#pragma unroll
        for (int j = 0; j < 8; j++) {
            oacc[j][0] *= f_lo; oacc[j][1] *= f_lo;
            oacc[j][2] *= f_hi; oacc[j][3] *= f_hi;
        }

#pragma unroll
        for (int t = 0; t < 4; t++) {
            u32 ph[4], pl[4];
            bsplit2(sacc[2 * t][0],     sacc[2 * t][1],     ph[0], pl[0]);
            bsplit2(sacc[2 * t][2],     sacc[2 * t][3],     ph[1], pl[1]);
            bsplit2(sacc[2 * t + 1][0], sacc[2 * t + 1][1], ph[2], pl[2]);
            bsplit2(sacc[2 * t + 1][2], sacc[2 * t + 1][3], ph[3], pl[3]);
#pragma unroll
            for (int up = 0; up < 4; up++) {
                u32 h0, h1, h2, h3, l0, l1, l2, l3;
                const u32 addr = sb + 2 * A_MAT + ((t * 16 + v_row) * KP + up * 16 + v_col) * 2;
                ldsm_x4_t(h0, h1, h2, h3, addr);
                ldsm_x4_t(l0, l1, l2, l3, addr + A_MAT);
                mma16816(oacc[2 * up],     ph[0], ph[1], ph[2], ph[3], h0, h1);
                mma16816(oacc[2 * up],     pl[0], pl[1], pl[2], pl[3], h0, h1);
                mma16816(oacc[2 * up],     ph[0], ph[1], ph[2], ph[3], l0, l1);
                mma16816(oacc[2 * up + 1], ph[0], ph[1], ph[2], ph[3], h2, h3);
                mma16816(oacc[2 * up + 1], pl[0], pl[1], pl[2], pl[3], h2, h3);
                mma16816(oacc[2 * up + 1], ph[0], ph[1], ph[2], ph[3], l2, l3);
            }
        }
        __syncthreads();
    }

    const float il_lo = 1.f / l_lo, il_hi = 1.f / l_hi;
    const int r_lo = qt + w * 16 + (lane >> 2);
    const int r_hi = r_lo + 8;
    const int b = bh >> 4, h = bh & 15;
    const int colb = h * 64 + 2 * (lane & 3);
#pragma unroll
    for (int j = 0; j < 8; j++) {
        const int col = colb + j * 8;
        u32 hp, lp;
        bsplit2(oacc[j][0] * il_lo, oacc[j][1] * il_lo, hp, lp);
        size_t ofs = (size_t)(b * S_ + r_lo) * H_ + col;
        *(u32*)(aoh + ofs) = hp;
        *(u32*)(aol + ofs) = lp;
        bsplit2(oacc[j][2] * il_hi, oacc[j][3] * il_hi, hp, lp);
        ofs = (size_t)(b * S_ + r_hi) * H_ + col;
        *(u32*)(aoh + ofs) = hp;
        *(u32*)(aol + ofs) = lp;
    }
}

// ---------------------------------------------------------------------------
// kernel_launch
// ---------------------------------------------------------------------------
extern "C" void kernel_launch(void* const* d_in, const int* in_sizes, int n_in,
                              void* d_out, int out_size)
{
    const float* q  = (const float*)d_in[0];
    const float* k  = (const float*)d_in[1];
    const float* v  = (const float*)d_in[2];
    const float* wq = (const float*)d_in[3];
    const float* bq = (const float*)d_in[4];
    const float* wk = (const float*)d_in[5];
    const float* bk = (const float*)d_in[6];
    const float* wv = (const float*)d_in[7];
    const float* bv = (const float*)d_in[8];
    const float* wo = (const float*)d_in[9];
    const float* bo = (const float*)d_in[10];
    float* out = (float*)d_out;

    __nv_bfloat16 *qihi, *qilo, *kihi, *kilo, *vihi, *vilo;
    __nv_bfloat16 *qphi, *qplo, *kphi, *kplo, *vphi, *vplo;
    __nv_bfloat16 *wqhi, *wqlo, *wkhi, *wklo, *wvhi, *wvlo, *wohi, *wolo;
    cudaGetSymbolAddress((void**)&qihi, g_qihi); cudaGetSymbolAddress((void**)&qilo, g_qilo);
    cudaGetSymbolAddress((void**)&kihi, g_kihi); cudaGetSymbolAddress((void**)&kilo, g_kilo);
    cudaGetSymbolAddress((void**)&vihi, g_vihi); cudaGetSymbolAddress((void**)&vilo, g_vilo);
    cudaGetSymbolAddress((void**)&qphi, g_qphi); cudaGetSymbolAddress((void**)&qplo, g_qplo);
    cudaGetSymbolAddress((void**)&kphi, g_kphi); cudaGetSymbolAddress((void**)&kplo, g_kplo);
    cudaGetSymbolAddress((void**)&vphi, g_vphi); cudaGetSymbolAddress((void**)&vplo, g_vplo);
    cudaGetSymbolAddress((void**)&wqhi, g_wqhi); cudaGetSymbolAddress((void**)&wqlo, g_wqlo);
    cudaGetSymbolAddress((void**)&wkhi, g_wkhi); cudaGetSymbolAddress((void**)&wklo, g_wklo);
    cudaGetSymbolAddress((void**)&wvhi, g_wvhi); cudaGetSymbolAddress((void**)&wvlo, g_wvlo);
    cudaGetSymbolAddress((void**)&wohi, g_wohi); cudaGetSymbolAddress((void**)&wolo, g_wolo);
    __nv_bfloat16 *aohi = qihi, *aolo = qilo;   // AO reuses q-input split buffers

    const int gemm_smem = 2 * G_STG;     // 59,392 B
    const int attn_smem = 2 * A_STG;     // 73,728 B
    cudaFuncSetAttribute(mma_gemm_kernel, cudaFuncAttributeMaxDynamicSharedMemorySize, gemm_smem);
    cudaFuncSetAttribute(attn_mma_kernel, cudaFuncAttributeMaxDynamicSharedMemorySize, attn_smem);

    const int actBlocks = (NACT / 4 + 255) / 256;
    const int wgtBlocks = (NWGT / 4 + 255) / 256;

    convert3_kernel<<<dim3(actBlocks, 3), 256>>>(q, k, v,
        qihi, qilo, kihi, kilo, vihi, vilo, NACT / 4);
    convert4_kernel<<<dim3(wgtBlocks, 4), 256>>>(wq, wk, wv, wo,
        wqhi, wqlo, wkhi, wklo, wvhi, wvlo, wohi, wolo, NWGT / 4);

    dim3 gg(16, 64), bb(256);
    // Q projection scaled by (1/sqrt(D)) * log2(e) so softmax runs in ex2 domain
    mma_gemm_kernel<<<gg, bb, gemm_smem>>>(qihi, qilo, wqhi, wqlo, bq, nullptr, qphi, qplo, 1, 0.125f * LOG2E);
    mma_gemm_kernel<<<gg, bb, gemm_smem>>>(kihi, kilo, wkhi, wklo, bk, nullptr, kphi, kplo, 1, 1.0f);
    mma_gemm_kernel<<<gg, bb, gemm_smem>>>(vihi, vilo, wvhi, wvlo, bv, nullptr, vphi, vplo, 1, 1.0f);

    attn_mma_kernel<<<dim3(16, 64), 256, attn_smem>>>(qphi, qplo, kphi, kplo, vphi, vplo, aohi, aolo);

    mma_gemm_kernel<<<gg, bb, gemm_smem>>>(aohi, aolo, wohi, wolo, bo, out, nullptr, nullptr, 0, 1.0f);
}